// round 4
// baseline (speedup 1.0000x reference)
#include <cuda_runtime.h>
#include <math.h>

#define SEQ     16384
#define IN_DIM  512
#define HID     1024
#define OUT_DIM 256

#define NB      128     // scan blocks (<148 SMs => all co-resident)
#define RPB     8       // hidden rows per block
#define SCAN_T  256     // 8 warps, one row per warp
#define RING    8       // sync ring depth (max block skew is 1)

// ---- scratch (static __device__; no allocs anywhere) ----
__device__ float              g_xh[SEQ * HID];     // 64 MB  xh = input@Wxh.T + bias
__device__ float              g_outs[SEQ * HID];   // 64 MB  h_1..h_SEQ for GEMM3
__device__ unsigned long long g_sync[RING * HID];  // 64 KB  {tag,value} ring
__device__ float              g_h0[HID];
__device__ float              g_bias[HID];

// morally-strong 8-byte exchange (relaxed atomics, gpu scope)
__device__ __forceinline__ void st_relaxed_u64(unsigned long long* p,
                                               unsigned long long v) {
    asm volatile("st.relaxed.gpu.u64 [%0], %1;" :: "l"(p), "l"(v) : "memory");
}
__device__ __forceinline__ unsigned long long ld_relaxed_u64(
        const unsigned long long* p) {
    unsigned long long v;
    asm volatile("ld.relaxed.gpu.u64 %0, [%1];" : "=l"(v) : "l"(p) : "memory");
    return v;
}

// ---------------------------------------------------------------- reset ----
__global__ void reset_kernel(const float* __restrict__ hidden,
                             const float* __restrict__ wxb,
                             const float* __restrict__ whb,
                             const float* __restrict__ bh) {
    int i = threadIdx.x;  // 1024 threads
    g_h0[i]   = hidden[i];
    g_bias[i] = wxb[i] + whb[i] + bh[i];
#pragma unroll
    for (int j = 0; j < RING; j++)          // clear tags (replay-safe)
        g_sync[j * HID + i] = 0ull;
}

// --------------------------------------------------- generic NT fp32 GEMM --
// C[m][n] = sum_k A[m][k] * B[n][k] + bias[n]
__global__ void gemm_nt_bias(const float* __restrict__ A,
                             const float* __restrict__ B,
                             const float* __restrict__ bias,
                             float* __restrict__ C,
                             int M, int N, int K) {
    __shared__ float As[16][65];
    __shared__ float Bs[16][65];
    const int tid = threadIdx.x;
    const int bx = blockIdx.x;
    const int by = blockIdx.y;
    const int tm = (tid >> 4) << 2;
    const int tn = (tid & 15) << 2;
    const int lr = tid >> 2;
    const int lk = (tid & 3) << 2;

    const float* Ap = A + (size_t)(by * 64 + lr) * K + lk;
    const float* Bp = B + (size_t)(bx * 64 + lr) * K + lk;

    float acc[4][4] = {};

    for (int k0 = 0; k0 < K; k0 += 16) {
        float4 av = *(const float4*)(Ap + k0);
        float4 bv = *(const float4*)(Bp + k0);
        As[lk + 0][lr] = av.x; As[lk + 1][lr] = av.y;
        As[lk + 2][lr] = av.z; As[lk + 3][lr] = av.w;
        Bs[lk + 0][lr] = bv.x; Bs[lk + 1][lr] = bv.y;
        Bs[lk + 2][lr] = bv.z; Bs[lk + 3][lr] = bv.w;
        __syncthreads();
#pragma unroll
        for (int k = 0; k < 16; k++) {
            float ra[4], rb[4];
#pragma unroll
            for (int i = 0; i < 4; i++) ra[i] = As[k][tm + i];
#pragma unroll
            for (int j = 0; j < 4; j++) rb[j] = Bs[k][tn + j];
#pragma unroll
            for (int i = 0; i < 4; i++)
#pragma unroll
                for (int j = 0; j < 4; j++)
                    acc[i][j] += ra[i] * rb[j];
        }
        __syncthreads();
    }

    float bb[4];
#pragma unroll
    for (int j = 0; j < 4; j++) bb[j] = bias[bx * 64 + tn + j];
#pragma unroll
    for (int i = 0; i < 4; i++) {
        int row = by * 64 + tm + i;
        float* cp = C + (size_t)row * N + bx * 64 + tn;
#pragma unroll
        for (int j = 0; j < 4; j++) cp[j] = acc[i][j] + bb[j];
    }
}

// -------------------------------------------------- dataflow persistent scan
// Tagged relaxed-atomic handoff through an 8-slot L2-resident ring.
// Producer of row r at step t publishes {tag=t+1, h} to slot t%8; consumers
// accept a word only when its tag matches exactly. No barriers, no fences.
__global__ void __launch_bounds__(SCAN_T, 1)
scan_kernel(const float* __restrict__ Whh) {
    const int bid  = blockIdx.x;
    const int tid  = threadIdx.x;
    const int wid  = tid >> 5;
    const int lane = tid & 31;
    const int row  = bid * RPB + wid;

    // Whh row slice in registers: w4[k] = Whh[row][k*128 + lane*4 .. +3]
    float4 w4[8];
#pragma unroll
    for (int k = 0; k < 8; k++)
        w4[k] = *(const float4*)&Whh[(size_t)row * HID + k * 128 + lane * 4];

    __shared__ float hs[2][HID];

    // stage h_0
    {
        float4 v = *(const float4*)&g_h0[tid * 4];
        *(float4*)&hs[0][tid * 4] = v;
    }
    __syncthreads();

    // xh pipeline (lane 0 only), depth 3
    float xh_c = 0.f, xh_n1 = 0.f, xh_n2 = 0.f;
    if (lane == 0) {
        xh_c  = g_xh[row];
        xh_n1 = g_xh[(size_t)1 * HID + row];
        xh_n2 = g_xh[(size_t)2 * HID + row];
    }

#pragma unroll 1
    for (int t = 0; t < SEQ; t++) {
        const float* hb = hs[t & 1];

        // MV: acc = Whh[row] . h_t   (8 x LDS.128 per lane)
        float a0 = 0.f, a1 = 0.f, a2 = 0.f, a3 = 0.f;
#pragma unroll
        for (int k = 0; k < 8; k++) {
            float4 hv = *(const float4*)&hb[k * 128 + lane * 4];
            a0 = fmaf(w4[k].x, hv.x, a0);
            a1 = fmaf(w4[k].y, hv.y, a1);
            a2 = fmaf(w4[k].z, hv.z, a2);
            a3 = fmaf(w4[k].w, hv.w, a3);
        }
        float acc = (a0 + a1) + (a2 + a3);
#pragma unroll
        for (int o = 16; o > 0; o >>= 1)
            acc += __shfl_xor_sync(0xFFFFFFFFu, acc, o);

        if (lane == 0) {
            float hn = tanhf(xh_c + acc);
            // publish {tag, value} to the ring (strong), history (plain)
            unsigned long long w =
                ((unsigned long long)(unsigned)(t + 1) << 32) |
                (unsigned long long)__float_as_uint(hn);
            st_relaxed_u64(&g_sync[(size_t)(t & (RING - 1)) * HID + row], w);
            g_outs[(size_t)t * HID + row] = hn;
            // rotate xh pipeline
            xh_c = xh_n1; xh_n1 = xh_n2;
            if (t + 3 < SEQ) xh_n2 = __ldg(&g_xh[(size_t)(t + 3) * HID + row]);
        }

        // gather h_{t+1}: thread tid handles rows tid + j*256 (coalesced 8B)
        if (t + 1 < SEQ) {
            const unsigned long long* base =
                g_sync + (size_t)(t & (RING - 1)) * HID;
            const unsigned tag = (unsigned)(t + 1);
            float* dst = hs[(t + 1) & 1];
#pragma unroll
            for (int j = 0; j < 4; j++) {
                const int r = tid + j * 256;
                unsigned long long w = ld_relaxed_u64(base + r);
                while ((unsigned)(w >> 32) != tag)
                    w = ld_relaxed_u64(base + r);
                dst[r] = __uint_as_float((unsigned)w);
            }
        }
        __syncthreads();
    }
}

// ----------------------------------------------------------- row softmax ---
__global__ void softmax256(float* __restrict__ X) {
    const int r = blockIdx.x;
    const int tid = threadIdx.x;          // 256
    const int wid = tid >> 5, lane = tid & 31;
    __shared__ float red[8];

    float v = X[(size_t)r * OUT_DIM + tid];

    float m = v;
#pragma unroll
    for (int o = 16; o > 0; o >>= 1)
        m = fmaxf(m, __shfl_xor_sync(0xFFFFFFFFu, m, o));
    if (lane == 0) red[wid] = m;
    __syncthreads();
    if (tid == 0) {
        float mm = red[0];
#pragma unroll
        for (int i = 1; i < 8; i++) mm = fmaxf(mm, red[i]);
        red[0] = mm;
    }
    __syncthreads();
    const float bm = red[0];
    __syncthreads();

    float e = expf(v - bm);
    float s = e;
#pragma unroll
    for (int o = 16; o > 0; o >>= 1)
        s += __shfl_xor_sync(0xFFFFFFFFu, s, o);
    if (lane == 0) red[wid] = s;
    __syncthreads();
    if (tid == 0) {
        float ss = red[0];
#pragma unroll
        for (int i = 1; i < 8; i++) ss += red[i];
        red[0] = ss;
    }
    __syncthreads();
    X[(size_t)r * OUT_DIM + tid] = e / red[0];
}

// ------------------------------------------------------------------ launch -
extern "C" void kernel_launch(void* const* d_in, const int* in_sizes, int n_in,
                              void* d_out, int out_size) {
    const float* input  = (const float*)d_in[0];   // (SEQ, IN)
    const float* hidden = (const float*)d_in[1];   // (HID,)
    const float* Wxh_w  = (const float*)d_in[2];   // (HID, IN)
    const float* Wxh_b  = (const float*)d_in[3];   // (HID,)
    const float* Whh_w  = (const float*)d_in[4];   // (HID, HID)
    const float* Whh_b  = (const float*)d_in[5];   // (HID,)
    const float* bh     = (const float*)d_in[6];   // (HID,)
    const float* fc_w   = (const float*)d_in[7];   // (OUT, HID)
    const float* fc_b   = (const float*)d_in[8];   // (OUT,)
    float* out = (float*)d_out;                    // (SEQ, OUT)

    float* xh_ptr   = nullptr;
    float* outs_ptr = nullptr;
    float* bias_ptr = nullptr;
    cudaGetSymbolAddress((void**)&xh_ptr,   g_xh);
    cudaGetSymbolAddress((void**)&outs_ptr, g_outs);
    cudaGetSymbolAddress((void**)&bias_ptr, g_bias);

    // 0) clear ring tags + fold biases + stage h0 (every launch => replay-safe)
    reset_kernel<<<1, HID>>>(hidden, Wxh_b, Whh_b, bh);

    // 1) xh = input @ Wxh.T + bias        (M=SEQ, N=HID, K=IN)
    {
        dim3 grid(HID / 64, SEQ / 64);
        gemm_nt_bias<<<grid, 256>>>(input, Wxh_w, bias_ptr, xh_ptr,
                                    SEQ, HID, IN_DIM);
    }

    // 2) sequential recurrence (tagged dataflow persistent kernel)
    scan_kernel<<<NB, SCAN_T>>>(Whh_w);

    // 3) logits = outs @ fc_w.T + fc_b    (M=SEQ, N=OUT, K=HID) -> d_out
    {
        dim3 grid(OUT_DIM / 64, SEQ / 64);
        gemm_nt_bias<<<grid, 256>>>(outs_ptr, fc_w, fc_b, out,
                                    SEQ, OUT_DIM, HID);
    }

    // 4) softmax rows in place on d_out
    softmax256<<<SEQ, OUT_DIM>>>(out);
}